// round 1
// baseline (speedup 1.0000x reference)
#include <cuda_runtime.h>
#include <cstdint>
#include <cstddef>

#define NROWS 16384
#define KCB   8192
#define DDIM  256
#define D2    128      // DDIM/2 (float2-packed)
#define BM    128
#define BN    128
#define CHUNK 8        // d2 values per B chunk
#define NCHUNK (D2/CHUNK)

// ---------------- scratch (static device allocations; no cudaMalloc) ----------------
__device__ float2 g_flatT[(size_t)D2 * NROWS];  // x normalized, [d2][row] packed pairs (16 MB)
__device__ float2 g_embnT[(size_t)D2 * KCB];    // embed normalized, [d2][col] packed pairs (8 MB)
__device__ float  g_denx[NROWS];
__device__ float  g_dene[KCB];
__device__ int    g_ind[NROWS];
__device__ float  g_bins[KCB];
__device__ float  g_esum[(size_t)KCB * DDIM];   // 8 MB

// ---------------- smem / packed-fp32 helpers ----------------
__device__ __forceinline__ void sts64(uint32_t a, unsigned long long v) {
    asm volatile("st.shared.b64 [%0], %1;" :: "r"(a), "l"(v));
}
__device__ __forceinline__ unsigned long long lds64(uint32_t a) {
    unsigned long long v;
    asm volatile("ld.shared.b64 %0, [%1];" : "=l"(v) : "r"(a));
    return v;
}
__device__ __forceinline__ void lds64x2(uint32_t a, unsigned long long& x, unsigned long long& y) {
    asm volatile("ld.shared.v2.b64 {%0, %1}, [%2];" : "=l"(x), "=l"(y) : "r"(a));
}
// packed fp32 pair FMA: d.lo += a.lo*b.lo ; d.hi += a.hi*b.hi
__device__ __forceinline__ void ffma2(unsigned long long& d, unsigned long long a, unsigned long long b) {
    asm("fma.rn.f32x2 %0, %1, %2, %0;" : "+l"(d) : "l"(a), "l"(b));
}

// ---------------- K0: normalize x rows -> g_flatT (transposed, packed) ----------------
__global__ void k_norm_x(const float* __restrict__ x) {
    int w = (blockIdx.x * blockDim.x + threadIdx.x) >> 5;   // row
    int lane = threadIdx.x & 31;
    if (w >= NROWS) return;
    const float2* x2 = (const float2*)x;
    float2 v[4];
    float s = 0.f;
#pragma unroll
    for (int i = 0; i < 4; i++) {
        v[i] = x2[(size_t)w * D2 + i * 32 + lane];
        s += v[i].x * v[i].x + v[i].y * v[i].y;
    }
#pragma unroll
    for (int off = 16; off >= 1; off >>= 1) s += __shfl_xor_sync(0xffffffffu, s, off);
    float den = fmaxf(__fsqrt_rn(s), 1e-12f);
#pragma unroll
    for (int i = 0; i < 4; i++) {
        int d2 = i * 32 + lane;
        float2 o;
        o.x = __fdiv_rn(v[i].x, den);
        o.y = __fdiv_rn(v[i].y, den);
        g_flatT[(size_t)d2 * NROWS + w] = o;
    }
    if (lane == 0) g_denx[w] = den;
}

// ---------------- K1: normalize embed rows -> g_embnT (transposed, packed) ----------------
__global__ void k_norm_e(const float* __restrict__ e) {
    int w = (blockIdx.x * blockDim.x + threadIdx.x) >> 5;   // codeword
    int lane = threadIdx.x & 31;
    if (w >= KCB) return;
    const float2* e2 = (const float2*)e;
    float2 v[4];
    float s = 0.f;
#pragma unroll
    for (int i = 0; i < 4; i++) {
        v[i] = e2[(size_t)w * D2 + i * 32 + lane];
        s += v[i].x * v[i].x + v[i].y * v[i].y;
    }
#pragma unroll
    for (int off = 16; off >= 1; off >>= 1) s += __shfl_xor_sync(0xffffffffu, s, off);
    float den = fmaxf(__fsqrt_rn(s), 1e-12f);
#pragma unroll
    for (int i = 0; i < 4; i++) {
        int d2 = i * 32 + lane;
        float2 o;
        o.x = __fdiv_rn(v[i].x, den);
        o.y = __fdiv_rn(v[i].y, den);
        g_embnT[(size_t)d2 * KCB + w] = o;
    }
    if (lane == 0) g_dene[w] = den;
}

// ---------------- K3: zero accumulators ----------------
__global__ void k_zero() {
    int i = blockIdx.x * blockDim.x + threadIdx.x;
    for (int j = i; j < KCB * DDIM; j += gridDim.x * blockDim.x) g_esum[j] = 0.f;
    if (i < KCB) g_bins[i] = 0.f;
}

// ---------------- K2: fused fp32 GEMM (f32x2 packed) + running argmax ----------------
// grid 128 blocks x 256 threads; block handles 128 rows x ALL 8192 cols.
extern "C" __global__ void __launch_bounds__(256, 1)
k_dist_argmax() {
    extern __shared__ unsigned char smem_raw[];
    uint32_t sb = (uint32_t)__cvta_generic_to_shared(smem_raw);
    const uint32_t BOFF = (uint32_t)D2 * BM * 8;   // A tile bytes = 131072

    int tid = threadIdx.x;
    int tx = tid & 15, ty = tid >> 4;
    int rowblk = blockIdx.x * BM;
    int r0 = ty * 8;

    const unsigned long long* flatT = (const unsigned long long*)g_flatT;
    const unsigned long long* embnT = (const unsigned long long*)g_embnT;

    // load A tile resident: As[d2*BM + r]  (i == d2*BM + r)
    for (int i = tid; i < D2 * BM; i += 256) {
        int d2 = i >> 7, r = i & (BM - 1);
        sts64(sb + (uint32_t)i * 8, flatT[(size_t)d2 * NROWS + rowblk + r]);
    }
    __syncthreads();

    float runb[8];
    int   runi[8];
#pragma unroll
    for (int i = 0; i < 8; i++) { runb[i] = -3.4e38f; runi[i] = 0; }

    for (int kt = 0; kt < KCB; kt += BN) {
        unsigned long long acc[8][8];
#pragma unroll
        for (int i = 0; i < 8; i++)
#pragma unroll
            for (int j = 0; j < 8; j++) acc[i][j] = 0ull;

        // prefetch B chunk 0 (coalesced: consecutive tid -> consecutive col)
        unsigned long long pre[4];
#pragma unroll
        for (int li = 0; li < 4; li++) {
            int idx = li * 256 + tid;
            int col = idx & (BN - 1), d2i = idx >> 7;
            pre[li] = embnT[(size_t)d2i * KCB + kt + col];
        }

        for (int s = 0; s < NCHUNK; s++) {
            uint32_t bbase = sb + BOFF + (uint32_t)(s & 1) * (CHUNK * BN * 8);
#pragma unroll
            for (int li = 0; li < 4; li++) {
                int idx = li * 256 + tid;
                sts64(bbase + (uint32_t)idx * 8, pre[li]);
            }
            __syncthreads();   // buf[s&1] ready; also fences reuse of buf[(s+1)&1]

            if (s + 1 < NCHUNK) {
                int ds = (s + 1) * CHUNK;
#pragma unroll
                for (int li = 0; li < 4; li++) {
                    int idx = li * 256 + tid;
                    int col = idx & (BN - 1), d2i = idx >> 7;
                    pre[li] = embnT[(size_t)(ds + d2i) * KCB + kt + col];
                }
            }

#pragma unroll
            for (int d2i = 0; d2i < CHUNK; d2i++) {
                unsigned long long a2[8], b2[8];
                uint32_t aaddr = sb + (uint32_t)((s * CHUNK + d2i) * BM + r0) * 8;
                lds64x2(aaddr,      a2[0], a2[1]);
                lds64x2(aaddr + 16, a2[2], a2[3]);
                lds64x2(aaddr + 32, a2[4], a2[5]);
                lds64x2(aaddr + 48, a2[6], a2[7]);
                uint32_t baddr = bbase + (uint32_t)(d2i * BN + tx) * 8;
#pragma unroll
                for (int j = 0; j < 8; j++) b2[j] = lds64(baddr + (uint32_t)j * 16 * 8);
#pragma unroll
                for (int i = 0; i < 8; i++)
#pragma unroll
                    for (int j = 0; j < 8; j++)
                        ffma2(acc[i][j], a2[i], b2[j]);
            }
        }

        // epilogue: per-row argmax over this 128-col tile, first-index tie-break
#pragma unroll
        for (int i = 0; i < 8; i++) {
            float best = -3.4e38f;
            int bi = 0;
#pragma unroll
            for (int j = 0; j < 8; j++) {   // ascending col => strict '>' keeps lowest idx
                unsigned long long v = acc[i][j];
                float c = __uint_as_float((unsigned)v) + __uint_as_float((unsigned)(v >> 32));
                int col = kt + tx + 16 * j;
                if (c > best) { best = c; bi = col; }
            }
#pragma unroll
            for (int off = 8; off >= 1; off >>= 1) {  // reduce across the 16 tx lanes
                float ob = __shfl_xor_sync(0xffffffffu, best, off);
                int   oi = __shfl_xor_sync(0xffffffffu, bi, off);
                if (ob > best || (ob == best && oi < bi)) { best = ob; bi = oi; }
            }
            if (best > runb[i] || (best == runb[i] && bi < runi[i])) { runb[i] = best; runi[i] = bi; }
        }
        __syncthreads();   // protect Bs buffers before next kt's first STS
    }

    if (tx == 0) {
#pragma unroll
        for (int i = 0; i < 8; i++) g_ind[rowblk + r0 + i] = runi[i];
    }
}

// ---------------- K4: quantize gather + index out + segment-sum scatter ----------------
__global__ void k_scatter(const float* __restrict__ x, const float* __restrict__ embed,
                          float* __restrict__ out_q, float* __restrict__ out_ind) {
    int n = blockIdx.x;
    int t = threadIdx.x;
    int ind = g_ind[n];
    float den = g_denx[n];
    float fl = __fdiv_rn(x[(size_t)n * DDIM + t], den);
    atomicAdd(&g_esum[(size_t)ind * DDIM + t], fl);
    out_q[(size_t)n * DDIM + t] = embed[(size_t)ind * DDIM + t];
    if (t == 0) {
        atomicAdd(&g_bins[ind], 1.0f);
        out_ind[n] = (float)ind;
    }
}

// ---------------- K5: EMA finalize -> embed_new ----------------
__global__ void k_final(const float* __restrict__ embed, float* __restrict__ out_e) {
    int w = (blockIdx.x * blockDim.x + threadIdx.x) >> 5;  // codeword
    int lane = threadIdx.x & 31;
    if (w >= KCB) return;
    float b = g_bins[w];
    bool zero = (b == 0.0f);
    float bs = zero ? 1.0f : b;
    float m[8];
    float s = 0.f;
#pragma unroll
    for (int i = 0; i < 8; i++) {
        int d = i * 32 + lane;
        m[i] = __fdiv_rn(g_esum[(size_t)w * DDIM + d], bs);
        s += m[i] * m[i];
    }
#pragma unroll
    for (int off = 16; off >= 1; off >>= 1) s += __shfl_xor_sync(0xffffffffu, s, off);
    float nrm = fmaxf(__fsqrt_rn(s), 1e-12f);
    float dene = g_dene[w];
#pragma unroll
    for (int i = 0; i < 8; i++) {
        int d = i * 32 + lane;
        float ev = embed[(size_t)w * DDIM + d];
        float en = zero ? __fdiv_rn(ev, dene) : __fdiv_rn(m[i], nrm);
        out_e[(size_t)w * DDIM + d] = ev * 0.8f + en * 0.2f;
    }
}

// ---------------- launcher ----------------
extern "C" void kernel_launch(void* const* d_in, const int* in_sizes, int n_in,
                              void* d_out, int out_size) {
    const float* x     = (const float*)d_in[0];
    const float* embed = (const float*)d_in[1];
    float* out     = (float*)d_out;
    float* out_q   = out;                               // [16384, 256]
    float* out_ind = out + (size_t)NROWS * DDIM;        // [16384]
    float* out_e   = out_ind + NROWS;                   // [8192, 256]

    (void)in_sizes; (void)n_in; (void)out_size;

    cudaFuncSetAttribute(k_dist_argmax, cudaFuncAttributeMaxDynamicSharedMemorySize, 147456);

    k_norm_x<<<NROWS / 8, 256>>>(x);
    k_norm_e<<<KCB / 8, 256>>>(embed);
    k_zero<<<2048, 256>>>();
    k_dist_argmax<<<NROWS / BM, 256, 147456>>>();
    k_scatter<<<NROWS, 256>>>(x, embed, out_q, out_ind);
    k_final<<<KCB / 8, 256>>>(embed, out_e);
}

// round 3
// speedup vs baseline: 4.4668x; 4.4668x over previous
#include <cuda_runtime.h>
#include <cuda_bf16.h>
#include <cstdint>
#include <cstddef>

#define NROWS 16384
#define KCB   8192
#define DDIM  256
#define BM    128
#define BN    128
#define NTILES (KCB / BN)            // 64
#define TILE_BYTES (BN * DDIM * 2)   // 65536 (B tile, bf16)
#define A_BYTES  (BM * DDIM * 2)     // 65536

// ---------------- static device scratch ----------------
__device__ __align__(16) unsigned int g_xB[(size_t)NROWS * 128];   // x normalized, bf16x2 row-major [row][128]
__device__ __align__(16) unsigned int g_eBn[(size_t)KCB * 128];    // embed normalized, bf16x2 row-major [n][128]
__device__ float g_flatn[(size_t)NROWS * DDIM];
__device__ float g_embn[(size_t)KCB * DDIM];
__device__ float g_denx[NROWS];
__device__ float g_dene[KCB];
__device__ int   g_cand[(size_t)NROWS * 32];
__device__ float g_cval[(size_t)NROWS * 32];
__device__ int   g_ind[NROWS];
__device__ float g_bins[KCB];
__device__ float g_esum[(size_t)KCB * DDIM];

// ---------------- PTX helpers (all plain-sm_100-legal) ----------------
#define CP_ASYNC16(dst, src) \
    asm volatile("cp.async.cg.shared.global [%0], [%1], 16;" :: "r"(dst), "l"(src))
#define CP_COMMIT() asm volatile("cp.async.commit_group;" ::: "memory")
#define CP_WAIT0()  asm volatile("cp.async.wait_group 0;" ::: "memory")
#define CP_WAIT1()  asm volatile("cp.async.wait_group 1;" ::: "memory")

__device__ __forceinline__ void ldsm4(uint32_t addr, uint32_t& r0, uint32_t& r1,
                                      uint32_t& r2, uint32_t& r3) {
    asm volatile("ldmatrix.sync.aligned.m8n8.x4.shared.b16 {%0,%1,%2,%3}, [%4];"
                 : "=r"(r0), "=r"(r1), "=r"(r2), "=r"(r3) : "r"(addr));
}

__device__ __forceinline__ void mma16816(float* c, const uint32_t* a, const uint32_t* b) {
    asm volatile("mma.sync.aligned.m16n8k16.row.col.f32.bf16.bf16.f32 "
                 "{%0,%1,%2,%3}, {%4,%5,%6,%7}, {%8,%9}, {%0,%1,%2,%3};"
                 : "+f"(c[0]), "+f"(c[1]), "+f"(c[2]), "+f"(c[3])
                 : "r"(a[0]), "r"(a[1]), "r"(a[2]), "r"(a[3]), "r"(b[0]), "r"(b[1]));
}

// ---------------- K0: normalize x rows -> g_flatn (fp32) + g_xB (bf16x2) ----------------
__global__ void k_norm_x(const float* __restrict__ x) {
    int w = (blockIdx.x * blockDim.x + threadIdx.x) >> 5;
    int lane = threadIdx.x & 31;
    if (w >= NROWS) return;
    const float2* x2 = (const float2*)x;
    float2 v[4];
    float s = 0.f;
#pragma unroll
    for (int i = 0; i < 4; i++) {
        v[i] = x2[(size_t)w * 128 + i * 32 + lane];
        s += v[i].x * v[i].x + v[i].y * v[i].y;
    }
#pragma unroll
    for (int off = 16; off >= 1; off >>= 1) s += __shfl_xor_sync(0xffffffffu, s, off);
    float den = fmaxf(__fsqrt_rn(s), 1e-12f);
#pragma unroll
    for (int i = 0; i < 4; i++) {
        int d2 = i * 32 + lane;
        float2 o;
        o.x = __fdiv_rn(v[i].x, den);
        o.y = __fdiv_rn(v[i].y, den);
        ((float2*)g_flatn)[(size_t)w * 128 + d2] = o;
        unsigned int u = ((unsigned int)__bfloat16_as_ushort(__float2bfloat16_rn(o.y)) << 16)
                       |  (unsigned int)__bfloat16_as_ushort(__float2bfloat16_rn(o.x));
        g_xB[(size_t)w * 128 + d2] = u;
    }
    if (lane == 0) g_denx[w] = den;
}

// ---------------- K1: normalize embed rows -> g_embn (fp32) + g_eBn (bf16x2) ----------------
__global__ void k_norm_e(const float* __restrict__ e) {
    int w = (blockIdx.x * blockDim.x + threadIdx.x) >> 5;
    int lane = threadIdx.x & 31;
    if (w >= KCB) return;
    const float2* e2 = (const float2*)e;
    float2 v[4];
    float s = 0.f;
#pragma unroll
    for (int i = 0; i < 4; i++) {
        v[i] = e2[(size_t)w * 128 + i * 32 + lane];
        s += v[i].x * v[i].x + v[i].y * v[i].y;
    }
#pragma unroll
    for (int off = 16; off >= 1; off >>= 1) s += __shfl_xor_sync(0xffffffffu, s, off);
    float den = fmaxf(__fsqrt_rn(s), 1e-12f);
#pragma unroll
    for (int i = 0; i < 4; i++) {
        int d2 = i * 32 + lane;
        float2 o;
        o.x = __fdiv_rn(v[i].x, den);
        o.y = __fdiv_rn(v[i].y, den);
        ((float2*)g_embn)[(size_t)w * 128 + d2] = o;
        unsigned int u = ((unsigned int)__bfloat16_as_ushort(__float2bfloat16_rn(o.y)) << 16)
                       |  (unsigned int)__bfloat16_as_ushort(__float2bfloat16_rn(o.x));
        g_eBn[(size_t)w * 128 + d2] = u;
    }
    if (lane == 0) g_dene[w] = den;
}

// ---------------- K3: zero accumulators ----------------
__global__ void k_zero() {
    int i = blockIdx.x * blockDim.x + threadIdx.x;
    for (int j = i; j < KCB * DDIM; j += gridDim.x * blockDim.x) g_esum[j] = 0.f;
    if (i < KCB) g_bins[i] = 0.f;
}

// ---------------- K2: HMMA bf16 GEMM + per-thread top-2 candidates ----------------
// smem: A (64KB, swizzled) | B0 (64KB) | B1 (64KB)
__global__ void __launch_bounds__(256, 1) k_gemm_top2() {
    extern __shared__ unsigned char smem[];
    uint32_t sb = (uint32_t)__cvta_generic_to_shared(smem);
    uint32_t sA  = sb;
    uint32_t sB0 = sb + A_BYTES;
    uint32_t sB1 = sb + A_BYTES + TILE_BYTES;

    int tid = threadIdx.x;
    int lane = tid & 31;
    int wid = tid >> 5;
    int wm = wid >> 2;          // 0..1 (row half)
    int wn = wid & 3;           // 0..3 (col quarter)
    int rowblk = blockIdx.x * BM;

    // ---- preload A tile + B tile 0 (group G0) ----
    {
        const char* srcA = (const char*)g_xB + (size_t)rowblk * 512;
        const char* srcB = (const char*)g_eBn;
#pragma unroll
        for (int q = 0; q < 16; q++) {
            int idx = tid + q * 256;
            int r = idx >> 5, c = idx & 31;
            uint32_t doff = (uint32_t)r * 512 + (uint32_t)((c ^ (r & 7)) << 4);
            CP_ASYNC16(sA + doff, srcA + (size_t)idx * 16);
        }
#pragma unroll
        for (int q = 0; q < 16; q++) {
            int idx = tid + q * 256;
            int r = idx >> 5, c = idx & 31;
            uint32_t doff = (uint32_t)r * 512 + (uint32_t)((c ^ (r & 7)) << 4);
            CP_ASYNC16(sB0 + doff, srcB + (size_t)idx * 16);
        }
        CP_COMMIT();
    }

    // ---- per-thread fragment address components ----
    // A: lane l -> row (l&15), k-half (l>>4). Addr per m-tile mt.
    uint32_t aRowB[4];
#pragma unroll
    for (int mt = 0; mt < 4; mt++)
        aRowB[mt] = sA + (uint32_t)(wm * 64 + mt * 16 + (lane & 15)) * 512;
    int swzA = (lane & 15) & 7;
    int khalfA = lane >> 4;
    // B: lane l -> ntile (l>>4), k-half ((l>>3)&1), row (l&7). Addr per n-pair ntp.
    uint32_t bRowOff[2];
#pragma unroll
    for (int ntp = 0; ntp < 2; ntp++)
        bRowOff[ntp] = (uint32_t)(wn * 32 + ntp * 16 + (lane >> 4) * 8 + (lane & 7)) * 512;
    int swzB = lane & 7;
    int khalfB = (lane >> 3) & 1;

    // ---- per-thread top-2 per row (8 rows: mt*2 + h) ----
    float v1[8], v2[8];
    int   i1[8], i2[8];
#pragma unroll
    for (int s = 0; s < 8; s++) { v1[s] = -3.4e38f; v2[s] = -3.4e38f; i1[s] = 0; i2[s] = 0; }

    for (int t = 0; t < NTILES; t++) {
        // prefetch tile t+1 into buffer (t+1)&1
        if (t + 1 < NTILES) {
            const char* srcB = (const char*)g_eBn + (size_t)(t + 1) * TILE_BYTES;
            uint32_t dst = ((t + 1) & 1) ? sB1 : sB0;
#pragma unroll
            for (int q = 0; q < 16; q++) {
                int idx = tid + q * 256;
                int r = idx >> 5, c = idx & 31;
                uint32_t doff = (uint32_t)r * 512 + (uint32_t)((c ^ (r & 7)) << 4);
                CP_ASYNC16(dst + doff, srcB + (size_t)idx * 16);
            }
            CP_COMMIT();
            CP_WAIT1();     // tile t's group complete; t+1's may be in flight
        } else {
            CP_WAIT0();
        }
        __syncthreads();

        uint32_t sB = (t & 1) ? sB1 : sB0;

        float acc[4][4][4];
#pragma unroll
        for (int mt = 0; mt < 4; mt++)
#pragma unroll
            for (int nt = 0; nt < 4; nt++)
#pragma unroll
                for (int cc = 0; cc < 4; cc++) acc[mt][nt][cc] = 0.f;

#pragma unroll
        for (int ks = 0; ks < 16; ks++) {
            uint32_t a[4][4];
            uint32_t offA = (uint32_t)(((ks * 2 + khalfA) ^ swzA) << 4);
#pragma unroll
            for (int mt = 0; mt < 4; mt++)
                ldsm4(aRowB[mt] + offA, a[mt][0], a[mt][1], a[mt][2], a[mt][3]);

            uint32_t b[4][2];
            uint32_t offB = (uint32_t)(((ks * 2 + khalfB) ^ swzB) << 4);
#pragma unroll
            for (int ntp = 0; ntp < 2; ntp++) {
                uint32_t r0, r1, r2, r3;
                ldsm4(sB + bRowOff[ntp] + offB, r0, r1, r2, r3);
                b[ntp * 2][0] = r0; b[ntp * 2][1] = r1;
                b[ntp * 2 + 1][0] = r2; b[ntp * 2 + 1][1] = r3;
            }
#pragma unroll
            for (int mt = 0; mt < 4; mt++)
#pragma unroll
                for (int nt = 0; nt < 4; nt++)
                    mma16816(acc[mt][nt], a[mt], b[nt]);
        }

        // epilogue: per-thread top-2 update over this tile's values
        int colq = t * BN + wn * 32 + 2 * (lane & 3);
#pragma unroll
        for (int mt = 0; mt < 4; mt++) {
#pragma unroll
            for (int nt = 0; nt < 4; nt++) {
                int c0 = colq + nt * 8;
#pragma unroll
                for (int h = 0; h < 2; h++) {
                    int lr = mt * 2 + h;
                    float va = acc[mt][nt][h * 2 + 0];
                    float vb = acc[mt][nt][h * 2 + 1];
                    if (va > v1[lr]) { v2[lr] = v1[lr]; i2[lr] = i1[lr]; v1[lr] = va; i1[lr] = c0; }
                    else if (va > v2[lr]) { v2[lr] = va; i2[lr] = c0; }
                    if (vb > v1[lr]) { v2[lr] = v1[lr]; i2[lr] = i1[lr]; v1[lr] = vb; i1[lr] = c0 + 1; }
                    else if (vb > v2[lr]) { v2[lr] = vb; i2[lr] = c0 + 1; }
                }
            }
        }
        __syncthreads();   // everyone done reading sB before next prefetch overwrites it
    }

    // write candidates: each row gets 32 slots = 16 threads x 2
    int slot = (wn * 4 + (lane & 3)) * 2;
#pragma unroll
    for (int mt = 0; mt < 4; mt++) {
#pragma unroll
        for (int h = 0; h < 2; h++) {
            int lr = mt * 2 + h;
            int row = rowblk + wm * 64 + mt * 16 + (lane >> 2) + h * 8;
            g_cand[(size_t)row * 32 + slot]     = i1[lr];
            g_cand[(size_t)row * 32 + slot + 1] = i2[lr];
            g_cval[(size_t)row * 32 + slot]     = v1[lr];
            g_cval[(size_t)row * 32 + slot + 1] = v2[lr];
        }
    }
}

// ---------------- K2b: margin-gated exact fp32 rescore ----------------
__global__ void k_rescore() {
    int r = blockIdx.x * 8 + (threadIdx.x >> 5);
    int lane = threadIdx.x & 31;
    if (r >= NROWS) return;
    const float4* fr = (const float4*)(g_flatn + (size_t)r * DDIM);
    float4 fa = fr[lane * 2], fb = fr[lane * 2 + 1];

    float cv = g_cval[(size_t)r * 32 + lane];
    int   ci = g_cand[(size_t)r * 32 + lane];
    float wmax = cv;
#pragma unroll
    for (int off = 16; off >= 1; off >>= 1) wmax = fmaxf(wmax, __shfl_xor_sync(0xffffffffu, wmax, off));
    unsigned m = __ballot_sync(0xffffffffu, cv >= wmax - 2.5e-3f);

    float best = -3.4e38f;
    int besti = 0x7fffffff;
    while (m) {
        int b = __ffs(m) - 1;
        m &= m - 1;
        int cj = __shfl_sync(0xffffffffu, ci, b);
        const float4* er = (const float4*)(g_embn + (size_t)cj * DDIM);
        float4 ea = er[lane * 2], eb = er[lane * 2 + 1];
        float s = fa.x * ea.x + fa.y * ea.y + fa.z * ea.z + fa.w * ea.w
                + fb.x * eb.x + fb.y * eb.y + fb.z * eb.z + fb.w * eb.w;
#pragma unroll
        for (int off = 16; off >= 1; off >>= 1) s += __shfl_xor_sync(0xffffffffu, s, off);
        if (s > best || (s == best && cj < besti)) { best = s; besti = cj; }
    }
    if (lane == 0) g_ind[r] = besti;
}

// ---------------- K4: quantize gather + index out + segment-sum scatter ----------------
__global__ void k_scatter(const float* __restrict__ x, const float* __restrict__ embed,
                          float* __restrict__ out_q, float* __restrict__ out_ind) {
    int n = blockIdx.x;
    int t = threadIdx.x;
    int ind = g_ind[n];
    float den = g_denx[n];
    float fl = __fdiv_rn(x[(size_t)n * DDIM + t], den);
    atomicAdd(&g_esum[(size_t)ind * DDIM + t], fl);
    out_q[(size_t)n * DDIM + t] = embed[(size_t)ind * DDIM + t];
    if (t == 0) {
        atomicAdd(&g_bins[ind], 1.0f);
        out_ind[n] = (float)ind;
    }
}

// ---------------- K5: EMA finalize -> embed_new ----------------
__global__ void k_final(const float* __restrict__ embed, float* __restrict__ out_e) {
    int w = (blockIdx.x * blockDim.x + threadIdx.x) >> 5;
    int lane = threadIdx.x & 31;
    if (w >= KCB) return;
    float b = g_bins[w];
    bool zero = (b == 0.0f);
    float bs = zero ? 1.0f : b;
    float m[8];
    float s = 0.f;
#pragma unroll
    for (int i = 0; i < 8; i++) {
        int d = i * 32 + lane;
        m[i] = __fdiv_rn(g_esum[(size_t)w * DDIM + d], bs);
        s += m[i] * m[i];
    }
#pragma unroll
    for (int off = 16; off >= 1; off >>= 1) s += __shfl_xor_sync(0xffffffffu, s, off);
    float nrm = fmaxf(__fsqrt_rn(s), 1e-12f);
    float dene = g_dene[w];
#pragma unroll
    for (int i = 0; i < 8; i++) {
        int d = i * 32 + lane;
        float ev = embed[(size_t)w * DDIM + d];
        float en = zero ? __fdiv_rn(ev, dene) : __fdiv_rn(m[i], nrm);
        out_e[(size_t)w * DDIM + d] = ev * 0.8f + en * 0.2f;
    }
}

// ---------------- launcher ----------------
extern "C" void kernel_launch(void* const* d_in, const int* in_sizes, int n_in,
                              void* d_out, int out_size) {
    const float* x     = (const float*)d_in[0];
    const float* embed = (const float*)d_in[1];
    float* out     = (float*)d_out;
    float* out_q   = out;                          // [16384, 256]
    float* out_ind = out + (size_t)NROWS * DDIM;   // [16384]
    float* out_e   = out_ind + NROWS;              // [8192, 256]

    (void)in_sizes; (void)n_in; (void)out_size;

    const int smem_bytes = A_BYTES + 2 * TILE_BYTES;   // 192 KB
    cudaFuncSetAttribute(k_gemm_top2, cudaFuncAttributeMaxDynamicSharedMemorySize, smem_bytes);

    k_norm_x<<<NROWS / 8, 256>>>(x);
    k_norm_e<<<KCB / 8, 256>>>(embed);
    k_zero<<<2048, 256>>>();
    k_gemm_top2<<<NROWS / BM, 256, smem_bytes>>>();
    k_rescore<<<NROWS / 8, 256>>>();
    k_scatter<<<NROWS, 256>>>(x, embed, out_q, out_ind);
    k_final<<<KCB / 8, 256>>>(embed, out_e);
}

// round 4
// speedup vs baseline: 5.1872x; 1.1613x over previous
#include <cuda_runtime.h>
#include <cuda_bf16.h>
#include <cstdint>
#include <cstddef>

#define NROWS 16384
#define KCB   8192
#define DDIM  256
#define BM    128
#define BN    128
#define NTILES (KCB / BN)            // 64
#define TILE_BYTES (BN * DDIM * 2)   // 65536 (B tile, bf16)
#define A_BYTES  (BM * DDIM * 2)     // 65536

// ---------------- static device scratch ----------------
__device__ __align__(16) unsigned int g_xB[(size_t)NROWS * 128];   // x normalized, bf16x2 row-major [row][128]
__device__ __align__(16) unsigned int g_eBn[(size_t)KCB * 128];    // embed normalized, bf16x2 row-major [n][128]
__device__ float g_flatn[(size_t)NROWS * DDIM];
__device__ float g_embn[(size_t)KCB * DDIM];
__device__ float g_denx[NROWS];
__device__ float g_dene[KCB];
__device__ int   g_cand[(size_t)NROWS * 32];
__device__ float g_cval[(size_t)NROWS * 32];
__device__ int   g_ind[NROWS];
__device__ float g_bins[KCB];
__device__ float g_esum[(size_t)KCB * DDIM];

// ---------------- PTX helpers (all plain-sm_100-legal) ----------------
#define CP_ASYNC16(dst, src) \
    asm volatile("cp.async.cg.shared.global [%0], [%1], 16;" :: "r"(dst), "l"(src))
#define CP_COMMIT() asm volatile("cp.async.commit_group;" ::: "memory")
#define CP_WAIT0()  asm volatile("cp.async.wait_group 0;" ::: "memory")
#define CP_WAIT1()  asm volatile("cp.async.wait_group 1;" ::: "memory")

__device__ __forceinline__ void ldsm4(uint32_t addr, uint32_t& r0, uint32_t& r1,
                                      uint32_t& r2, uint32_t& r3) {
    asm volatile("ldmatrix.sync.aligned.m8n8.x4.shared.b16 {%0,%1,%2,%3}, [%4];"
                 : "=r"(r0), "=r"(r1), "=r"(r2), "=r"(r3) : "r"(addr));
}

__device__ __forceinline__ void mma16816(float* c, const uint32_t* a, const uint32_t* b) {
    asm volatile("mma.sync.aligned.m16n8k16.row.col.f32.bf16.bf16.f32 "
                 "{%0,%1,%2,%3}, {%4,%5,%6,%7}, {%8,%9}, {%0,%1,%2,%3};"
                 : "+f"(c[0]), "+f"(c[1]), "+f"(c[2]), "+f"(c[3])
                 : "r"(a[0]), "r"(a[1]), "r"(a[2]), "r"(a[3]), "r"(b[0]), "r"(b[1]));
}

// ---------------- K0: normalize x rows -> g_flatn (fp32) + g_xB (bf16x2) ----------------
__global__ void k_norm_x(const float* __restrict__ x) {
    int w = (blockIdx.x * blockDim.x + threadIdx.x) >> 5;
    int lane = threadIdx.x & 31;
    if (w >= NROWS) return;
    const float2* x2 = (const float2*)x;
    float2 v[4];
    float s = 0.f;
#pragma unroll
    for (int i = 0; i < 4; i++) {
        v[i] = x2[(size_t)w * 128 + i * 32 + lane];
        s += v[i].x * v[i].x + v[i].y * v[i].y;
    }
#pragma unroll
    for (int off = 16; off >= 1; off >>= 1) s += __shfl_xor_sync(0xffffffffu, s, off);
    float den = fmaxf(__fsqrt_rn(s), 1e-12f);
#pragma unroll
    for (int i = 0; i < 4; i++) {
        int d2 = i * 32 + lane;
        float2 o;
        o.x = __fdiv_rn(v[i].x, den);
        o.y = __fdiv_rn(v[i].y, den);
        ((float2*)g_flatn)[(size_t)w * 128 + d2] = o;
        unsigned int u = ((unsigned int)__bfloat16_as_ushort(__float2bfloat16_rn(o.y)) << 16)
                       |  (unsigned int)__bfloat16_as_ushort(__float2bfloat16_rn(o.x));
        g_xB[(size_t)w * 128 + d2] = u;
    }
    if (lane == 0) g_denx[w] = den;
}

// ---------------- K1: normalize embed rows -> g_embn (fp32) + g_eBn (bf16x2) ----------------
__global__ void k_norm_e(const float* __restrict__ e) {
    int w = (blockIdx.x * blockDim.x + threadIdx.x) >> 5;
    int lane = threadIdx.x & 31;
    if (w >= KCB) return;
    const float2* e2 = (const float2*)e;
    float2 v[4];
    float s = 0.f;
#pragma unroll
    for (int i = 0; i < 4; i++) {
        v[i] = e2[(size_t)w * 128 + i * 32 + lane];
        s += v[i].x * v[i].x + v[i].y * v[i].y;
    }
#pragma unroll
    for (int off = 16; off >= 1; off >>= 1) s += __shfl_xor_sync(0xffffffffu, s, off);
    float den = fmaxf(__fsqrt_rn(s), 1e-12f);
#pragma unroll
    for (int i = 0; i < 4; i++) {
        int d2 = i * 32 + lane;
        float2 o;
        o.x = __fdiv_rn(v[i].x, den);
        o.y = __fdiv_rn(v[i].y, den);
        ((float2*)g_embn)[(size_t)w * 128 + d2] = o;
        unsigned int u = ((unsigned int)__bfloat16_as_ushort(__float2bfloat16_rn(o.y)) << 16)
                       |  (unsigned int)__bfloat16_as_ushort(__float2bfloat16_rn(o.x));
        g_eBn[(size_t)w * 128 + d2] = u;
    }
    if (lane == 0) g_dene[w] = den;
}

// ---------------- K3: zero accumulators ----------------
__global__ void k_zero() {
    int i = blockIdx.x * blockDim.x + threadIdx.x;
    for (int j = i; j < KCB * DDIM; j += gridDim.x * blockDim.x) g_esum[j] = 0.f;
    if (i < KCB) g_bins[i] = 0.f;
}

// ---------------- K2: HMMA bf16 GEMM + per-thread top-2 candidates ----------------
// 512 threads, 16 warps (4x4), warp tile 32x32.
// smem: A (64KB, swizzled) | B0 (64KB) | B1 (64KB)
__global__ void __launch_bounds__(512, 1) k_gemm_top2() {
    extern __shared__ unsigned char smem[];
    uint32_t sb = (uint32_t)__cvta_generic_to_shared(smem);
    uint32_t sA  = sb;
    uint32_t sB0 = sb + A_BYTES;
    uint32_t sB1 = sb + A_BYTES + TILE_BYTES;

    int tid = threadIdx.x;
    int lane = tid & 31;
    int wid = tid >> 5;
    int wm = wid >> 2;          // 0..3 (row 32-slab)
    int wn = wid & 3;           // 0..3 (col quarter)
    int rowblk = blockIdx.x * BM;

    // ---- preload A tile + B tile 0 (group G0) ----
    {
        const char* srcA = (const char*)g_xB + (size_t)rowblk * 512;
        const char* srcB = (const char*)g_eBn;
#pragma unroll
        for (int q = 0; q < 8; q++) {
            int idx = tid + q * 512;
            int r = idx >> 5, c = idx & 31;
            uint32_t doff = (uint32_t)r * 512 + (uint32_t)((c ^ (r & 7)) << 4);
            CP_ASYNC16(sA + doff, srcA + (size_t)idx * 16);
        }
#pragma unroll
        for (int q = 0; q < 8; q++) {
            int idx = tid + q * 512;
            int r = idx >> 5, c = idx & 31;
            uint32_t doff = (uint32_t)r * 512 + (uint32_t)((c ^ (r & 7)) << 4);
            CP_ASYNC16(sB0 + doff, srcB + (size_t)idx * 16);
        }
        CP_COMMIT();
    }

    // ---- per-thread fragment address components ----
    uint32_t aRowB[2];
#pragma unroll
    for (int mt = 0; mt < 2; mt++)
        aRowB[mt] = sA + (uint32_t)(wm * 32 + mt * 16 + (lane & 15)) * 512;
    int swzA = lane & 7;
    int khalfA = lane >> 4;
    uint32_t bRowOff[2];
#pragma unroll
    for (int ntp = 0; ntp < 2; ntp++)
        bRowOff[ntp] = (uint32_t)(wn * 32 + ntp * 16 + (lane >> 4) * 8 + (lane & 7)) * 512;
    int swzB = lane & 7;
    int khalfB = (lane >> 3) & 1;

    // ---- per-thread top-2 per row (4 rows: mt*2 + h) ----
    float v1[4], v2[4];
    int   i1[4], i2[4];
#pragma unroll
    for (int s = 0; s < 4; s++) { v1[s] = -3.4e38f; v2[s] = -3.4e38f; i1[s] = 0; i2[s] = 0; }

    for (int t = 0; t < NTILES; t++) {
        // prefetch tile t+1 into buffer (t+1)&1
        if (t + 1 < NTILES) {
            const char* srcB = (const char*)g_eBn + (size_t)(t + 1) * TILE_BYTES;
            uint32_t dst = ((t + 1) & 1) ? sB1 : sB0;
#pragma unroll
            for (int q = 0; q < 8; q++) {
                int idx = tid + q * 512;
                int r = idx >> 5, c = idx & 31;
                uint32_t doff = (uint32_t)r * 512 + (uint32_t)((c ^ (r & 7)) << 4);
                CP_ASYNC16(dst + doff, srcB + (size_t)idx * 16);
            }
            CP_COMMIT();
            CP_WAIT1();     // tile t's group complete; t+1's may be in flight
        } else {
            CP_WAIT0();
        }
        __syncthreads();

        uint32_t sB = (t & 1) ? sB1 : sB0;

        float acc[2][4][4];
#pragma unroll
        for (int mt = 0; mt < 2; mt++)
#pragma unroll
            for (int nt = 0; nt < 4; nt++)
#pragma unroll
                for (int cc = 0; cc < 4; cc++) acc[mt][nt][cc] = 0.f;

        // double-buffered fragments: load ks+1 while mma ks
        uint32_t a[2][2][4], b[2][4][2];
        {
            uint32_t offA = (uint32_t)((khalfA ^ swzA) << 4);
#pragma unroll
            for (int mt = 0; mt < 2; mt++)
                ldsm4(aRowB[mt] + offA, a[0][mt][0], a[0][mt][1], a[0][mt][2], a[0][mt][3]);
            uint32_t offB = (uint32_t)((khalfB ^ swzB) << 4);
#pragma unroll
            for (int ntp = 0; ntp < 2; ntp++) {
                uint32_t r0, r1, r2, r3;
                ldsm4(sB + bRowOff[ntp] + offB, r0, r1, r2, r3);
                b[0][ntp * 2][0] = r0; b[0][ntp * 2][1] = r1;
                b[0][ntp * 2 + 1][0] = r2; b[0][ntp * 2 + 1][1] = r3;
            }
        }

#pragma unroll
        for (int ks = 0; ks < 16; ks++) {
            int cur = ks & 1, nxt = cur ^ 1;
            if (ks < 15) {
                uint32_t offA = (uint32_t)((((ks + 1) * 2 + khalfA) ^ swzA) << 4);
#pragma unroll
                for (int mt = 0; mt < 2; mt++)
                    ldsm4(aRowB[mt] + offA, a[nxt][mt][0], a[nxt][mt][1], a[nxt][mt][2], a[nxt][mt][3]);
                uint32_t offB = (uint32_t)((((ks + 1) * 2 + khalfB) ^ swzB) << 4);
#pragma unroll
                for (int ntp = 0; ntp < 2; ntp++) {
                    uint32_t r0, r1, r2, r3;
                    ldsm4(sB + bRowOff[ntp] + offB, r0, r1, r2, r3);
                    b[nxt][ntp * 2][0] = r0; b[nxt][ntp * 2][1] = r1;
                    b[nxt][ntp * 2 + 1][0] = r2; b[nxt][ntp * 2 + 1][1] = r3;
                }
            }
#pragma unroll
            for (int mt = 0; mt < 2; mt++)
#pragma unroll
                for (int nt = 0; nt < 4; nt++)
                    mma16816(acc[mt][nt], a[cur][mt], b[cur][nt]);
        }

        // epilogue: per-thread top-2 update, fast-path gated on fmaxf(pair)
        int colq = t * BN + wn * 32 + 2 * (lane & 3);
#pragma unroll
        for (int mt = 0; mt < 2; mt++) {
#pragma unroll
            for (int nt = 0; nt < 4; nt++) {
                int c0 = colq + nt * 8;
#pragma unroll
                for (int h = 0; h < 2; h++) {
                    int lr = mt * 2 + h;
                    float va = acc[mt][nt][h * 2 + 0];
                    float vb = acc[mt][nt][h * 2 + 1];
                    if (fmaxf(va, vb) > v2[lr]) {
                        if (va > v1[lr]) { v2[lr] = v1[lr]; i2[lr] = i1[lr]; v1[lr] = va; i1[lr] = c0; }
                        else if (va > v2[lr]) { v2[lr] = va; i2[lr] = c0; }
                        if (vb > v1[lr]) { v2[lr] = v1[lr]; i2[lr] = i1[lr]; v1[lr] = vb; i1[lr] = c0 + 1; }
                        else if (vb > v2[lr]) { v2[lr] = vb; i2[lr] = c0 + 1; }
                    }
                }
            }
        }
        __syncthreads();   // everyone done reading sB before next prefetch overwrites it
    }

    // write candidates: each row gets 32 slots = 16 threads x 2
    int slot = (wn * 4 + (lane & 3)) * 2;
#pragma unroll
    for (int mt = 0; mt < 2; mt++) {
#pragma unroll
        for (int h = 0; h < 2; h++) {
            int lr = mt * 2 + h;
            int row = rowblk + wm * 32 + mt * 16 + (lane >> 2) + h * 8;
            g_cand[(size_t)row * 32 + slot]     = i1[lr];
            g_cand[(size_t)row * 32 + slot + 1] = i2[lr];
            g_cval[(size_t)row * 32 + slot]     = v1[lr];
            g_cval[(size_t)row * 32 + slot + 1] = v2[lr];
        }
    }
}

// ---------------- K2b: margin-gated exact fp32 rescore ----------------
__global__ void k_rescore() {
    int r = blockIdx.x * 8 + (threadIdx.x >> 5);
    int lane = threadIdx.x & 31;
    if (r >= NROWS) return;
    const float4* fr = (const float4*)(g_flatn + (size_t)r * DDIM);
    float4 fa = fr[lane * 2], fb = fr[lane * 2 + 1];

    float cv = g_cval[(size_t)r * 32 + lane];
    int   ci = g_cand[(size_t)r * 32 + lane];
    float wmax = cv;
#pragma unroll
    for (int off = 16; off >= 1; off >>= 1) wmax = fmaxf(wmax, __shfl_xor_sync(0xffffffffu, wmax, off));
    unsigned m = __ballot_sync(0xffffffffu, cv >= wmax - 2.5e-3f);

    float best = -3.4e38f;
    int besti = 0x7fffffff;
    while (m) {
        int b = __ffs(m) - 1;
        m &= m - 1;
        int cj = __shfl_sync(0xffffffffu, ci, b);
        const float4* er = (const float4*)(g_embn + (size_t)cj * DDIM);
        float4 ea = er[lane * 2], eb = er[lane * 2 + 1];
        float s = fa.x * ea.x + fa.y * ea.y + fa.z * ea.z + fa.w * ea.w
                + fb.x * eb.x + fb.y * eb.y + fb.z * eb.z + fb.w * eb.w;
#pragma unroll
        for (int off = 16; off >= 1; off >>= 1) s += __shfl_xor_sync(0xffffffffu, s, off);
        if (s > best || (s == best && cj < besti)) { best = s; besti = cj; }
    }
    if (lane == 0) g_ind[r] = besti;
}

// ---------------- K4: quantize gather + index out + segment-sum scatter ----------------
__global__ void k_scatter(const float* __restrict__ x, const float* __restrict__ embed,
                          float* __restrict__ out_q, float* __restrict__ out_ind) {
    int n = blockIdx.x;
    int t = threadIdx.x;
    int ind = g_ind[n];
    float den = g_denx[n];
    float fl = __fdiv_rn(x[(size_t)n * DDIM + t], den);
    atomicAdd(&g_esum[(size_t)ind * DDIM + t], fl);
    out_q[(size_t)n * DDIM + t] = embed[(size_t)ind * DDIM + t];
    if (t == 0) {
        atomicAdd(&g_bins[ind], 1.0f);
        out_ind[n] = (float)ind;
    }
}

// ---------------- K5: EMA finalize -> embed_new ----------------
__global__ void k_final(const float* __restrict__ embed, float* __restrict__ out_e) {
    int w = (blockIdx.x * blockDim.x + threadIdx.x) >> 5;
    int lane = threadIdx.x & 31;
    if (w >= KCB) return;
    float b = g_bins[w];
    bool zero = (b == 0.0f);
    float bs = zero ? 1.0f : b;
    float m[8];
    float s = 0.f;
#pragma unroll
    for (int i = 0; i < 8; i++) {
        int d = i * 32 + lane;
        m[i] = __fdiv_rn(g_esum[(size_t)w * DDIM + d], bs);
        s += m[i] * m[i];
    }
#pragma unroll
    for (int off = 16; off >= 1; off >>= 1) s += __shfl_xor_sync(0xffffffffu, s, off);
    float nrm = fmaxf(__fsqrt_rn(s), 1e-12f);
    float dene = g_dene[w];
#pragma unroll
    for (int i = 0; i < 8; i++) {
        int d = i * 32 + lane;
        float ev = embed[(size_t)w * DDIM + d];
        float en = zero ? __fdiv_rn(ev, dene) : __fdiv_rn(m[i], nrm);
        out_e[(size_t)w * DDIM + d] = ev * 0.8f + en * 0.2f;
    }
}

// ---------------- launcher ----------------
extern "C" void kernel_launch(void* const* d_in, const int* in_sizes, int n_in,
                              void* d_out, int out_size) {
    const float* x     = (const float*)d_in[0];
    const float* embed = (const float*)d_in[1];
    float* out     = (float*)d_out;
    float* out_q   = out;                          // [16384, 256]
    float* out_ind = out + (size_t)NROWS * DDIM;   // [16384]
    float* out_e   = out_ind + NROWS;              // [8192, 256]

    (void)in_sizes; (void)n_in; (void)out_size;

    const int smem_bytes = A_BYTES + 2 * TILE_BYTES;   // 192 KB
    cudaFuncSetAttribute(k_gemm_top2, cudaFuncAttributeMaxDynamicSharedMemorySize, smem_bytes);

    k_norm_x<<<NROWS / 8, 256>>>(x);
    k_norm_e<<<KCB / 8, 256>>>(embed);
    k_zero<<<2048, 256>>>();
    k_gemm_top2<<<NROWS / BM, 512, smem_bytes>>>();
    k_rescore<<<NROWS / 8, 256>>>();
    k_scatter<<<NROWS, 256>>>(x, embed, out_q, out_ind);
    k_final<<<KCB / 8, 256>>>(embed, out_e);
}